// round 6
// baseline (speedup 1.0000x reference)
#include <cuda_runtime.h>
#include <cstdint>
#include <math.h>

#define MB 8192
#define NB 4096
#define KB 2048
#define HDIM 1024

#define BM 128
#define BN 256
#define BK 32
#define STAGES 3
#define NSLABS (KB / BK)            // 64

#define A_TILE_BYTES (BM * BK * 4)  // 16384
#define B_TILE_BYTES (BN * BK * 4)  // 32768
#define STAGE_BYTES (A_TILE_BYTES + B_TILE_BYTES)      // 49152
#define SMEM_TOTAL (STAGES * STAGE_BYTES)              // 147456
#define EPI_PITCH 260                                  // floats per row

// Scratch: tf32-rounded packed operands
__device__ float g_A[(size_t)MB * KB];      // 64 MB  [x | h_prev]
__device__ float g_W[(size_t)NB * KB];      // 32 MB  gate-interleaved [Wx|Wh]

// ---------------------------------------------------------------------------
// PTX helpers
// ---------------------------------------------------------------------------
__device__ __forceinline__ uint32_t smem_u32(const void* p) {
    uint32_t a;
    asm("{ .reg .u64 t; cvta.to.shared.u64 t, %1; cvt.u32.u64 %0, t; }"
        : "=r"(a) : "l"(p));
    return a;
}

#define CP_ASYNC16(dst, src) \
    asm volatile("cp.async.cg.shared.global [%0], [%1], 16;" \
                 :: "r"(dst), "l"(src) : "memory")
#define CP_COMMIT() asm volatile("cp.async.commit_group;" ::: "memory")
#define CP_WAIT(n)  asm volatile("cp.async.wait_group %0;" :: "n"(n) : "memory")

#define LDM_X4(r0, r1, r2, r3, addr) \
    asm volatile("ldmatrix.sync.aligned.m8n8.x4.shared.b16 {%0,%1,%2,%3}, [%4];" \
                 : "=r"(r0), "=r"(r1), "=r"(r2), "=r"(r3) : "r"(addr))

#define MMA_TF32(d, a, b0, b1) \
    asm volatile("mma.sync.aligned.m16n8k8.row.col.f32.tf32.tf32.f32 " \
                 "{%0,%1,%2,%3}, {%4,%5,%6,%7}, {%8,%9}, {%0,%1,%2,%3};" \
                 : "+f"((d)[0]), "+f"((d)[1]), "+f"((d)[2]), "+f"((d)[3]) \
                 : "r"((a)[0]), "r"((a)[1]), "r"((a)[2]), "r"((a)[3]), \
                   "r"(b0), "r"(b1))

// XOR swizzle on (row, 16B-col) within a [rows x 128B] tile
__device__ __forceinline__ uint32_t swz(int row, int c16) {
    return (uint32_t)(row * 128 + ((c16 ^ (row & 7)) << 4));
}

__device__ __forceinline__ float sigmoidf_(float v) {
    return 1.0f / (1.0f + expf(-v));
}

// ---------------------------------------------------------------------------
// Pre-pass: rna-round to tf32 once.
//   g_A row m        = [x[m] | h_prev[m]]
//   g_W packed row p : p = (h>>6)*256 + gate*64 + (h&63)  <- W[gate*1024+h]
// ---------------------------------------------------------------------------
#define A4TOT ((size_t)MB * KB / 4)   // 4194304
#define W4TOT ((size_t)NB * KB / 4)   // 2097152

__global__ __launch_bounds__(256)
void pack_tf32(const float* __restrict__ x, const float* __restrict__ h,
               const float* __restrict__ Wx, const float* __restrict__ Wh)
{
    size_t idx = (size_t)blockIdx.x * blockDim.x + threadIdx.x;
    if (idx >= A4TOT + W4TOT) return;

    const float* src;
    float* dst;
    if (idx < A4TOT) {
        size_t row = idx >> 9;
        int col = (int)(idx & 511) << 2;
        src = (col < HDIM) ? (x + row * HDIM + col)
                           : (h + row * HDIM + col - HDIM);
        dst = g_A + (row << 11) + col;
    } else {
        size_t w = idx - A4TOT;
        size_t p = w >> 9;
        int col = (int)(w & 511) << 2;
        int hblk = (int)(p >> 8);
        int gate = (int)((p >> 6) & 3);
        int hoff = (int)(p & 63);
        size_t srow = (size_t)gate * 1024 + hblk * 64 + hoff;
        src = (col < HDIM) ? (Wx + srow * HDIM + col)
                           : (Wh + srow * HDIM + col - HDIM);
        dst = g_W + (p << 11) + col;
    }
    float4 v = *reinterpret_cast<const float4*>(src);
    uint32_t t0, t1, t2, t3;
    asm volatile("cvt.rna.tf32.f32 %0, %1;" : "=r"(t0) : "f"(v.x));
    asm volatile("cvt.rna.tf32.f32 %0, %1;" : "=r"(t1) : "f"(v.y));
    asm volatile("cvt.rna.tf32.f32 %0, %1;" : "=r"(t2) : "f"(v.z));
    asm volatile("cvt.rna.tf32.f32 %0, %1;" : "=r"(t3) : "f"(v.w));
    float4 o;
    o.x = __uint_as_float(t0); o.y = __uint_as_float(t1);
    o.z = __uint_as_float(t2); o.w = __uint_as_float(t3);
    *reinterpret_cast<float4*>(dst) = o;
}

// ---------------------------------------------------------------------------
// Fused GEMM + LSTM cell.
// CTA 128x256x32, 3-stage cp.async, 256 threads = 8 warps (2m x 4n),
// warp tile 64x64 (warp_n == gate), acc 128 regs -> deep per-warp ILP.
// ---------------------------------------------------------------------------
__global__ __launch_bounds__(256, 1)
void lstm_fused(const float* __restrict__ bias,
                const float* __restrict__ c_prev,
                float* __restrict__ out)
{
    extern __shared__ char smem[];
    const uint32_t tiles = smem_u32(smem);

    const int tid = threadIdx.x;
    const int wid = tid >> 5;
    const int lid = tid & 31;
    const int warp_m = wid & 1;        // 2 warps along M (64 rows)
    const int warp_n = wid >> 1;       // 4 warps along N (64 cols) == gate
    const int block_m = blockIdx.y * BM;
    const int block_n = blockIdx.x * BN;   // packed-W row base
    const int H0 = blockIdx.x * 64;        // h-column base

    float c[4][8][4];
#pragma unroll
    for (int i = 0; i < 4; i++)
#pragma unroll
        for (int j = 0; j < 8; j++)
#pragma unroll
            for (int q = 0; q < 4; q++)
                c[i][j][q] = 0.0f;

    // cp.async mapping: A 1024 chunks (4/thread), B 2048 chunks (8/thread)
    const int ld_r   = tid >> 3;       // 0..31
    const int ld_c16 = tid & 7;

    auto load_stage = [&](int stg, int slab) {
        const int kk = slab * BK;
        const float* Asrc = g_A + kk;
        const float* Bsrc = g_W + kk;
        const uint32_t ab = tiles + stg * STAGE_BYTES;
        const uint32_t bb = ab + A_TILE_BYTES;
#pragma unroll
        for (int t = 0; t < 4; t++) {
            const int r = ld_r + t * 32;
            CP_ASYNC16(ab + swz(r, ld_c16),
                       Asrc + (size_t)(block_m + r) * KB + ld_c16 * 4);
        }
#pragma unroll
        for (int t = 0; t < 8; t++) {
            const int r = ld_r + t * 32;
            CP_ASYNC16(bb + swz(r, ld_c16),
                       Bsrc + (size_t)(block_n + r) * KB + ld_c16 * 4);
        }
    };

#pragma unroll
    for (int s = 0; s < STAGES - 1; s++) {
        load_stage(s, s);
        CP_COMMIT();
    }

    const int a_row_in = (lid & 7) + ((lid >> 3) & 1) * 8;
    const int a_hi     = (lid >> 4) & 1;
    const int b_row_in = (lid & 7) + ((lid >> 4) & 1) * 8;
    const int b_hi     = (lid >> 3) & 1;

    for (int slab = 0; slab < NSLABS; slab++) {
        CP_WAIT(STAGES - 2);
        __syncthreads();

        const int next = slab + (STAGES - 1);
        if (next < NSLABS) load_stage(next % STAGES, next);
        CP_COMMIT();

        const int stg = slab % STAGES;
        const uint32_t Abase = tiles + stg * STAGE_BYTES;
        const uint32_t Bbase = Abase + A_TILE_BYTES;

#pragma unroll
        for (int ks = 0; ks < 4; ks++) {
            uint32_t a[4][4];
#pragma unroll
            for (int mi = 0; mi < 4; mi++) {
                const int row = warp_m * 64 + mi * 16 + a_row_in;
                LDM_X4(a[mi][0], a[mi][1], a[mi][2], a[mi][3],
                       Abase + swz(row, ks * 2 + a_hi));
            }
            uint32_t b[4][4];
#pragma unroll
            for (int j = 0; j < 4; j++) {
                const int row = warp_n * 64 + j * 16 + b_row_in;
                LDM_X4(b[j][0], b[j][1], b[j][2], b[j][3],
                       Bbase + swz(row, ks * 2 + b_hi));
            }
#pragma unroll
            for (int mi = 0; mi < 4; mi++)
#pragma unroll
                for (int ni = 0; ni < 8; ni++)
                    MMA_TF32(c[mi][ni], a[mi],
                             b[ni >> 1][(ni & 1) * 2],
                             b[ni >> 1][(ni & 1) * 2 + 1]);
        }
    }

    // =================== fused epilogue ===================
    CP_WAIT(0);
    __syncthreads();   // mainloop smem reads done; reuse tile smem
    float* ep = reinterpret_cast<float*>(smem);

    // Phase 1: acc + bias -> smem, gate-interleaved:
    //   float idx = row*EPI_PITCH + 4*(hh ^ (row&7)) + gate
    const int g8 = lid >> 2;
    const int q  = lid & 3;
    const int gate = warp_n;
    const float* brow = bias + gate * 1024 + H0;
#pragma unroll
    for (int ni = 0; ni < 8; ni++) {
        const int hh = ni * 8 + q * 2;
        const float b0 = __ldg(brow + hh);
        const float b1 = __ldg(brow + hh + 1);
#pragma unroll
        for (int mi = 0; mi < 4; mi++) {
            const int row0 = warp_m * 64 + mi * 16 + g8;
#pragma unroll
            for (int half = 0; half < 2; half++) {
                const int row = row0 + half * 8;
                const int xr = row & 7;
                ep[row * EPI_PITCH + 4 * (hh ^ xr) + gate]
                    = c[mi][ni][half * 2 + 0] + b0;
                ep[row * EPI_PITCH + 4 * ((hh + 1) ^ xr) + gate]
                    = c[mi][ni][half * 2 + 1] + b1;
            }
        }
    }
    __syncthreads();

    // Phase 2: LSTM math. warp w -> rows [16w, 16w+16); lane -> h = lid, lid+32
#pragma unroll
    for (int r = 0; r < 16; r++) {
        const int m = wid * 16 + r;
        const int xr = m & 7;
        const size_t gbase = (size_t)(block_m + m) * HDIM + H0;
#pragma unroll
        for (int hi2 = 0; hi2 < 2; hi2++) {
            const int h = lid + 32 * hi2;
            float4 v = *reinterpret_cast<const float4*>(
                ep + m * EPI_PITCH + 4 * (h ^ xr));
            // v = (i, f, o, g)
            const float cp = __ldg(c_prev + gbase + h);
            const float ct = sigmoidf_(v.y) * cp + sigmoidf_(v.x) * tanhf(v.w);
            const float ht = sigmoidf_(v.z) * tanhf(ct);
            out[gbase + h] = ht;
            out[(size_t)MB * HDIM + gbase + h] = ct;
        }
    }
}

extern "C" void kernel_launch(void* const* d_in, const int* in_sizes, int n_in,
                              void* d_out, int out_size)
{
    const float* x      = (const float*)d_in[0];
    const float* h_prev = (const float*)d_in[1];
    const float* c_prev = (const float*)d_in[2];
    const float* Wx     = (const float*)d_in[3];
    const float* Wh     = (const float*)d_in[4];
    const float* bias   = (const float*)d_in[5];
    float* out = (float*)d_out;

    size_t packtot = A4TOT + W4TOT;
    pack_tf32<<<(int)((packtot + 255) / 256), 256>>>(x, h_prev, Wx, Wh);

    cudaFuncSetAttribute(lstm_fused,
                         cudaFuncAttributeMaxDynamicSharedMemorySize, SMEM_TOTAL);
    dim3 grid(NB / BN, MB / BM);   // (16, 64)
    lstm_fused<<<grid, 256, SMEM_TOTAL>>>(bias, c_prev, out);
}

// round 7
// speedup vs baseline: 1.8821x; 1.8821x over previous
#include <cuda_runtime.h>
#include <cuda_fp16.h>
#include <cstdint>
#include <math.h>

#define MB 8192
#define NB 4096
#define KB 2048
#define HDIM 1024

#define BM 128
#define BN 256
#define BK 64                        // fp16 elements per slab (128B rows)
#define STAGES 3
#define NSLABS (KB / BK)             // 32

#define A_TILE_BYTES (BM * BK * 2)   // 16384
#define B_TILE_BYTES (BN * BK * 2)   // 32768
#define STAGE_BYTES (A_TILE_BYTES + B_TILE_BYTES)      // 49152
#define SMEM_TOTAL (STAGES * STAGE_BYTES)              // 147456
#define EPI_PITCH 260                                  // floats per row

// Scratch: fp16 packed operands
__device__ __half g_A[(size_t)MB * KB];      // 32 MB  [x | h_prev]
__device__ __half g_W[(size_t)NB * KB];      // 16 MB  gate-interleaved [Wx|Wh]

__device__ __forceinline__ uint32_t smem_u32(const void* p) {
    uint32_t a;
    asm("{ .reg .u64 t; cvta.to.shared.u64 t, %1; cvt.u32.u64 %0, t; }"
        : "=r"(a) : "l"(p));
    return a;
}

#define CP_ASYNC16(dst, src) \
    asm volatile("cp.async.cg.shared.global [%0], [%1], 16;" \
                 :: "r"(dst), "l"(src) : "memory")
#define CP_COMMIT() asm volatile("cp.async.commit_group;" ::: "memory")
#define CP_WAIT(n)  asm volatile("cp.async.wait_group %0;" :: "n"(n) : "memory")

#define LDM_X4(r0, r1, r2, r3, addr) \
    asm volatile("ldmatrix.sync.aligned.m8n8.x4.shared.b16 {%0,%1,%2,%3}, [%4];" \
                 : "=r"(r0), "=r"(r1), "=r"(r2), "=r"(r3) : "r"(addr))

#define MMA_F16(d, a, b0, b1) \
    asm volatile("mma.sync.aligned.m16n8k16.row.col.f32.f16.f16.f32 " \
                 "{%0,%1,%2,%3}, {%4,%5,%6,%7}, {%8,%9}, {%0,%1,%2,%3};" \
                 : "+f"((d)[0]), "+f"((d)[1]), "+f"((d)[2]), "+f"((d)[3]) \
                 : "r"((a)[0]), "r"((a)[1]), "r"((a)[2]), "r"((a)[3]), \
                   "r"(b0), "r"(b1))

__device__ __forceinline__ uint32_t swz(int row, int c16) {
    return (uint32_t)(row * 128 + ((c16 ^ (row & 7)) << 4));
}

__device__ __forceinline__ float sigmoidf_(float v) {
    return 1.0f / (1.0f + expf(-v));
}

// ---------------------------------------------------------------------------
// Pre-pass: round to fp16 once (rne; fp16 mantissa == tf32 mantissa).
//   g_A row m        = [x[m] | h_prev[m]]
//   g_W packed row p : p = (h>>6)*256 + gate*64 + (h&63)  <- W[gate*1024+h]
// ---------------------------------------------------------------------------
#define A4TOT ((size_t)MB * KB / 4)   // 4194304
#define W4TOT ((size_t)NB * KB / 4)   // 2097152

__global__ __launch_bounds__(256)
void pack_f16(const float* __restrict__ x, const float* __restrict__ h,
              const float* __restrict__ Wx, const float* __restrict__ Wh)
{
    size_t idx = (size_t)blockIdx.x * blockDim.x + threadIdx.x;
    if (idx >= A4TOT + W4TOT) return;

    const float* src;
    __half* dst;
    if (idx < A4TOT) {
        size_t row = idx >> 9;
        int col = (int)(idx & 511) << 2;
        src = (col < HDIM) ? (x + row * HDIM + col)
                           : (h + row * HDIM + col - HDIM);
        dst = g_A + (row << 11) + col;
    } else {
        size_t w = idx - A4TOT;
        size_t p = w >> 9;
        int col = (int)(w & 511) << 2;
        int hblk = (int)(p >> 8);
        int gate = (int)((p >> 6) & 3);
        int hoff = (int)(p & 63);
        size_t srow = (size_t)gate * 1024 + hblk * 64 + hoff;
        src = (col < HDIM) ? (Wx + srow * HDIM + col)
                           : (Wh + srow * HDIM + col - HDIM);
        dst = g_W + (p << 11) + col;
    }
    float4 v = *reinterpret_cast<const float4*>(src);
    __half2 h01 = __floats2half2_rn(v.x, v.y);
    __half2 h23 = __floats2half2_rn(v.z, v.w);
    uint2 o;
    o.x = *reinterpret_cast<uint32_t*>(&h01);
    o.y = *reinterpret_cast<uint32_t*>(&h23);
    *reinterpret_cast<uint2*>(dst) = o;
}

// ---------------------------------------------------------------------------
// Fused GEMM + LSTM cell.
// CTA 128x256xk64 fp16, 3-stage cp.async, 512 threads = 16 warps (4m x 4n),
// warp tile 32x64 (warp_n == gate). mma.m16n8k16.f16, fp32 accum.
// ---------------------------------------------------------------------------
__global__ __launch_bounds__(512, 1)
void lstm_fused(const float* __restrict__ bias,
                const float* __restrict__ c_prev,
                float* __restrict__ out)
{
    extern __shared__ char smem[];
    const uint32_t tiles = smem_u32(smem);

    const int tid = threadIdx.x;
    const int wid = tid >> 5;
    const int lid = tid & 31;
    const int warp_m = wid & 3;        // 4 warps along M (32 rows)
    const int warp_n = wid >> 2;       // 4 warps along N (64 cols) == gate
    const int block_m = blockIdx.y * BM;
    const int block_n = blockIdx.x * BN;   // packed-W row base
    const int H0 = blockIdx.x * 64;        // h-column base

    float c[2][8][4];
#pragma unroll
    for (int i = 0; i < 2; i++)
#pragma unroll
        for (int j = 0; j < 8; j++)
#pragma unroll
            for (int q = 0; q < 4; q++)
                c[i][j][q] = 0.0f;

    const int ld_r   = tid >> 3;       // 0..63
    const int ld_c16 = tid & 7;

    auto load_stage = [&](int stg, int slab) {
        const int kk = slab * BK;
        const __half* Asrc = g_A + kk;
        const __half* Bsrc = g_W + kk;
        const uint32_t ab = tiles + stg * STAGE_BYTES;
        const uint32_t bb = ab + A_TILE_BYTES;
#pragma unroll
        for (int t = 0; t < 2; t++) {
            const int r = ld_r + t * 64;
            CP_ASYNC16(ab + swz(r, ld_c16),
                       Asrc + (size_t)(block_m + r) * KB + ld_c16 * 8);
        }
#pragma unroll
        for (int t = 0; t < 4; t++) {
            const int r = ld_r + t * 64;
            CP_ASYNC16(bb + swz(r, ld_c16),
                       Bsrc + (size_t)(block_n + r) * KB + ld_c16 * 8);
        }
    };

#pragma unroll
    for (int s = 0; s < STAGES - 1; s++) {
        load_stage(s, s);
        CP_COMMIT();
    }

    const int a_row_in = lid & 15;               // m within m16
    const int a_hi     = (lid >> 4) & 1;         // k8 half
    const int b_row_in = (lid & 7) + ((lid >> 4) & 1) * 8;   // n within n16
    const int b_hi     = (lid >> 3) & 1;         // k8 half

    for (int slab = 0; slab < NSLABS; slab++) {
        CP_WAIT(STAGES - 2);
        __syncthreads();

        const int next = slab + (STAGES - 1);
        if (next < NSLABS) load_stage(next % STAGES, next);
        CP_COMMIT();

        const int stg = slab % STAGES;
        const uint32_t Abase = tiles + stg * STAGE_BYTES;
        const uint32_t Bbase = Abase + A_TILE_BYTES;

#pragma unroll
        for (int ks = 0; ks < 4; ks++) {         // 4 x k16 per k64 slab
            uint32_t a[2][4];
#pragma unroll
            for (int mi = 0; mi < 2; mi++) {
                const int row = warp_m * 32 + mi * 16 + a_row_in;
                LDM_X4(a[mi][0], a[mi][1], a[mi][2], a[mi][3],
                       Abase + swz(row, ks * 2 + a_hi));
            }
            uint32_t b[4][4];                     // 8 n8k16 frags (2 per x4)
#pragma unroll
            for (int j = 0; j < 4; j++) {
                const int row = warp_n * 64 + j * 16 + b_row_in;
                LDM_X4(b[j][0], b[j][1], b[j][2], b[j][3],
                       Bbase + swz(row, ks * 2 + b_hi));
            }
#pragma unroll
            for (int mi = 0; mi < 2; mi++)
#pragma unroll
                for (int ni = 0; ni < 8; ni++)
                    MMA_F16(c[mi][ni], a[mi],
                            b[ni >> 1][(ni & 1) * 2],
                            b[ni >> 1][(ni & 1) * 2 + 1]);
        }
    }

    // =================== fused epilogue (validated in R5) ===================
    CP_WAIT(0);
    __syncthreads();
    float* ep = reinterpret_cast<float*>(smem);

    const int g8 = lid >> 2;
    const int q  = lid & 3;
    const int gate = warp_n;
    const float* brow = bias + gate * 1024 + H0;
#pragma unroll
    for (int ni = 0; ni < 8; ni++) {
        const int hh = ni * 8 + q * 2;
        const float b0 = __ldg(brow + hh);
        const float b1 = __ldg(brow + hh + 1);
#pragma unroll
        for (int mi = 0; mi < 2; mi++) {
            const int row0 = warp_m * 32 + mi * 16 + g8;
#pragma unroll
            for (int half = 0; half < 2; half++) {
                const int row = row0 + half * 8;
                const int xr = row & 7;
                ep[row * EPI_PITCH + 4 * (hh ^ xr) + gate]
                    = c[mi][ni][half * 2 + 0] + b0;
                ep[row * EPI_PITCH + 4 * ((hh + 1) ^ xr) + gate]
                    = c[mi][ni][half * 2 + 1] + b1;
            }
        }
    }
    __syncthreads();

#pragma unroll
    for (int r = 0; r < 8; r++) {
        const int m = wid * 8 + r;
        const int xr = m & 7;
        const size_t gbase = (size_t)(block_m + m) * HDIM + H0;
#pragma unroll
        for (int hi2 = 0; hi2 < 2; hi2++) {
            const int h = lid + 32 * hi2;
            float4 v = *reinterpret_cast<const float4*>(
                ep + m * EPI_PITCH + 4 * (h ^ xr));
            const float cp = __ldg(c_prev + gbase + h);
            const float ct = sigmoidf_(v.y) * cp + sigmoidf_(v.x) * tanhf(v.w);
            const float ht = sigmoidf_(v.z) * tanhf(ct);
            out[gbase + h] = ht;
            out[(size_t)MB * HDIM + gbase + h] = ct;
        }
    }
}

extern "C" void kernel_launch(void* const* d_in, const int* in_sizes, int n_in,
                              void* d_out, int out_size)
{
    const float* x      = (const float*)d_in[0];
    const float* h_prev = (const float*)d_in[1];
    const float* c_prev = (const float*)d_in[2];
    const float* Wx     = (const float*)d_in[3];
    const float* Wh     = (const float*)d_in[4];
    const float* bias   = (const float*)d_in[5];
    float* out = (float*)d_out;

    size_t packtot = A4TOT + W4TOT;
    pack_f16<<<(int)((packtot + 255) / 256), 256>>>(x, h_prev, Wx, Wh);

    cudaFuncSetAttribute(lstm_fused,
                         cudaFuncAttributeMaxDynamicSharedMemorySize, SMEM_TOTAL);
    dim3 grid(NB / BN, MB / BM);   // (16, 64)
    lstm_fused<<<grid, 512, SMEM_TOTAL>>>(bias, c_prev, out);
}

// round 8
// speedup vs baseline: 2.0770x; 1.1036x over previous
#include <cuda_runtime.h>
#include <cuda_fp16.h>
#include <cstdint>
#include <math.h>

#define MB 8192
#define NB 4096
#define KB 2048
#define HDIM 1024

#define BM 128
#define BN 128                       // 4 gates x 32 h-columns
#define BK 64                        // fp16 elements per slab (128B rows)
#define STAGES 3
#define NSLABS (KB / BK)             // 32

#define A_TILE_BYTES (BM * BK * 2)   // 16384
#define B_TILE_BYTES (BN * BK * 2)   // 16384
#define STAGE_BYTES (A_TILE_BYTES + B_TILE_BYTES)      // 32768
#define SMEM_TOTAL (STAGES * STAGE_BYTES)              // 98304 (2 CTAs/SM)
#define EPI_PITCH 132                                  // floats per row (128+4 pad)

// Scratch: fp16 packed operands
__device__ __half g_A[(size_t)MB * KB];      // 32 MB  [x | h_prev]
__device__ __half g_W[(size_t)NB * KB];      // 16 MB  gate-interleaved [Wx|Wh]

__device__ __forceinline__ uint32_t smem_u32(const void* p) {
    uint32_t a;
    asm("{ .reg .u64 t; cvta.to.shared.u64 t, %1; cvt.u32.u64 %0, t; }"
        : "=r"(a) : "l"(p));
    return a;
}

#define CP_ASYNC16(dst, src) \
    asm volatile("cp.async.cg.shared.global [%0], [%1], 16;" \
                 :: "r"(dst), "l"(src) : "memory")
#define CP_COMMIT() asm volatile("cp.async.commit_group;" ::: "memory")
#define CP_WAIT(n)  asm volatile("cp.async.wait_group %0;" :: "n"(n) : "memory")

#define LDM_X4(r0, r1, r2, r3, addr) \
    asm volatile("ldmatrix.sync.aligned.m8n8.x4.shared.b16 {%0,%1,%2,%3}, [%4];" \
                 : "=r"(r0), "=r"(r1), "=r"(r2), "=r"(r3) : "r"(addr))

#define MMA_F16(d, a, b0, b1) \
    asm volatile("mma.sync.aligned.m16n8k16.row.col.f32.f16.f16.f32 " \
                 "{%0,%1,%2,%3}, {%4,%5,%6,%7}, {%8,%9}, {%0,%1,%2,%3};" \
                 : "+f"((d)[0]), "+f"((d)[1]), "+f"((d)[2]), "+f"((d)[3]) \
                 : "r"((a)[0]), "r"((a)[1]), "r"((a)[2]), "r"((a)[3]), \
                   "r"(b0), "r"(b1))

// XOR swizzle on (row, 16B-col) within a [rows x 128B] tile
__device__ __forceinline__ uint32_t swz(int row, int c16) {
    return (uint32_t)(row * 128 + ((c16 ^ (row & 7)) << 4));
}

__device__ __forceinline__ float sigmoidf_(float v) {
    return 1.0f / (1.0f + expf(-v));
}

// ---------------------------------------------------------------------------
// Pre-pass: round to fp16 once (rne).
//   g_A row m        = [x[m] | h_prev[m]]
//   g_W packed row p : p = (h>>5)*128 + gate*32 + (h&31)  <- W[gate*1024+h]
// so each GEMM CTA's 128 B-rows = the 4 gate rows of one 32-wide h block.
// ---------------------------------------------------------------------------
#define A4TOT ((size_t)MB * KB / 4)   // 4194304
#define W4TOT ((size_t)NB * KB / 4)   // 2097152

__global__ __launch_bounds__(256)
void pack_f16(const float* __restrict__ x, const float* __restrict__ h,
              const float* __restrict__ Wx, const float* __restrict__ Wh)
{
    size_t idx = (size_t)blockIdx.x * blockDim.x + threadIdx.x;
    if (idx >= A4TOT + W4TOT) return;

    const float* src;
    __half* dst;
    if (idx < A4TOT) {
        size_t row = idx >> 9;
        int col = (int)(idx & 511) << 2;
        src = (col < HDIM) ? (x + row * HDIM + col)
                           : (h + row * HDIM + col - HDIM);
        dst = g_A + (row << 11) + col;
    } else {
        size_t w = idx - A4TOT;
        size_t p = w >> 9;
        int col = (int)(w & 511) << 2;
        int hblk = (int)(p >> 7);          // 0..31
        int gate = (int)((p >> 5) & 3);
        int hoff = (int)(p & 31);
        size_t srow = (size_t)gate * 1024 + hblk * 32 + hoff;
        src = (col < HDIM) ? (Wx + srow * HDIM + col)
                           : (Wh + srow * HDIM + col - HDIM);
        dst = g_W + (p << 11) + col;
    }
    float4 v = *reinterpret_cast<const float4*>(src);
    __half2 h01 = __floats2half2_rn(v.x, v.y);
    __half2 h23 = __floats2half2_rn(v.z, v.w);
    uint2 o;
    o.x = *reinterpret_cast<uint32_t*>(&h01);
    o.y = *reinterpret_cast<uint32_t*>(&h23);
    *reinterpret_cast<uint2*>(dst) = o;
}

// ---------------------------------------------------------------------------
// Fused GEMM + LSTM cell.
// CTA 128x128xk64 fp16, 3-stage cp.async, 256 threads = 8 warps (2m x 4n),
// warp tile 64x32 (warp_n == gate). 2 CTAs/SM for decoupled pipelines.
// ---------------------------------------------------------------------------
__global__ __launch_bounds__(256, 2)
void lstm_fused(const float* __restrict__ bias,
                const float* __restrict__ c_prev,
                float* __restrict__ out)
{
    extern __shared__ char smem[];
    const uint32_t tiles = smem_u32(smem);

    const int tid = threadIdx.x;
    const int wid = tid >> 5;
    const int lid = tid & 31;
    const int warp_m = wid & 1;        // 2 warps along M (64 rows)
    const int warp_n = wid >> 1;       // 4 warps along N (32 cols) == gate
    const int block_m = blockIdx.y * BM;
    const int block_n = blockIdx.x * BN;   // packed-W row base
    const int H0 = blockIdx.x * 32;        // h-column base

    float c[4][4][4];                  // [mi][ni][quad] = 64 regs
#pragma unroll
    for (int i = 0; i < 4; i++)
#pragma unroll
        for (int j = 0; j < 4; j++)
#pragma unroll
            for (int q = 0; q < 4; q++)
                c[i][j][q] = 0.0f;

    // cp.async mapping: A and B each 1024 x 16B chunks, 4 per thread per tile
    const int ld_r   = tid >> 3;       // 0..31
    const int ld_c16 = tid & 7;

    auto load_stage = [&](int stg, int slab) {
        const int kk = slab * BK;
        const __half* Asrc = g_A + kk;
        const __half* Bsrc = g_W + kk;
        const uint32_t ab = tiles + stg * STAGE_BYTES;
        const uint32_t bb = ab + A_TILE_BYTES;
#pragma unroll
        for (int t = 0; t < 4; t++) {
            const int r = ld_r + t * 32;
            CP_ASYNC16(ab + swz(r, ld_c16),
                       Asrc + (size_t)(block_m + r) * KB + ld_c16 * 8);
            CP_ASYNC16(bb + swz(r, ld_c16),
                       Bsrc + (size_t)(block_n + r) * KB + ld_c16 * 8);
        }
    };

#pragma unroll
    for (int s = 0; s < STAGES - 1; s++) {
        load_stage(s, s);
        CP_COMMIT();
    }

    const int a_row_in = lid & 15;               // m within m16
    const int a_hi     = (lid >> 4) & 1;         // k8 half
    const int b_row_in = (lid & 7) + ((lid >> 4) & 1) * 8;   // n within n16
    const int b_hi     = (lid >> 3) & 1;         // k8 half

    for (int slab = 0; slab < NSLABS; slab++) {
        CP_WAIT(STAGES - 2);
        __syncthreads();

        const int next = slab + (STAGES - 1);
        if (next < NSLABS) load_stage(next % STAGES, next);
        CP_COMMIT();

        const int stg = slab % STAGES;
        const uint32_t Abase = tiles + stg * STAGE_BYTES;
        const uint32_t Bbase = Abase + A_TILE_BYTES;

#pragma unroll
        for (int ks = 0; ks < 4; ks++) {         // 4 x k16 per k64 slab
            uint32_t a[4][4];
#pragma unroll
            for (int mi = 0; mi < 4; mi++) {
                const int row = warp_m * 64 + mi * 16 + a_row_in;
                LDM_X4(a[mi][0], a[mi][1], a[mi][2], a[mi][3],
                       Abase + swz(row, ks * 2 + a_hi));
            }
            uint32_t b[2][4];                     // 4 n8k16 frags
#pragma unroll
            for (int j = 0; j < 2; j++) {
                const int row = warp_n * 32 + j * 16 + b_row_in;
                LDM_X4(b[j][0], b[j][1], b[j][2], b[j][3],
                       Bbase + swz(row, ks * 2 + b_hi));
            }
#pragma unroll
            for (int mi = 0; mi < 4; mi++)
#pragma unroll
                for (int ni = 0; ni < 4; ni++)
                    MMA_F16(c[mi][ni], a[mi],
                            b[ni >> 1][(ni & 1) * 2],
                            b[ni >> 1][(ni & 1) * 2 + 1]);
        }
    }

    // =================== fused epilogue ===================
    CP_WAIT(0);
    __syncthreads();   // mainloop smem reads done; reuse tile smem
    float* ep = reinterpret_cast<float*>(smem);   // 128 x EPI_PITCH floats

    // Phase 1: acc + bias -> smem, gate-interleaved:
    //   float idx = row*EPI_PITCH + 4*(hh ^ (row&7)) + gate    (hh in 0..31)
    const int g8 = lid >> 2;
    const int q  = lid & 3;
    const int gate = warp_n;
    const float* brow = bias + gate * 1024 + H0;
#pragma unroll
    for (int ni = 0; ni < 4; ni++) {
        const int hh = ni * 8 + q * 2;
        const float b0 = __ldg(brow + hh);
        const float b1 = __ldg(brow + hh + 1);
#pragma unroll
        for (int mi = 0; mi < 4; mi++) {
            const int row0 = warp_m * 64 + mi * 16 + g8;
#pragma unroll
            for (int half = 0; half < 2; half++) {
                const int row = row0 + half * 8;
                const int xr = row & 7;
                ep[row * EPI_PITCH + 4 * (hh ^ xr) + gate]
                    = c[mi][ni][half * 2 + 0] + b0;
                ep[row * EPI_PITCH + 4 * ((hh + 1) ^ xr) + gate]
                    = c[mi][ni][half * 2 + 1] + b1;
            }
        }
    }
    __syncthreads();

    // Phase 2: LSTM math. warp w -> rows [16w, 16w+16); lane -> h = lid (0..31)
#pragma unroll
    for (int r = 0; r < 16; r++) {
        const int m = wid * 16 + r;
        const int xr = m & 7;
        const size_t gbase = (size_t)(block_m + m) * HDIM + H0;
        const int h = lid;
        float4 v = *reinterpret_cast<const float4*>(
            ep + m * EPI_PITCH + 4 * (h ^ xr));
        // v = (i, f, o, g)
        const float cp = __ldg(c_prev + gbase + h);
        const float ct = sigmoidf_(v.y) * cp + sigmoidf_(v.x) * tanhf(v.w);
        const float ht = sigmoidf_(v.z) * tanhf(ct);
        out[gbase + h] = ht;
        out[(size_t)MB * HDIM + gbase + h] = ct;
    }
}

extern "C" void kernel_launch(void* const* d_in, const int* in_sizes, int n_in,
                              void* d_out, int out_size)
{
    const float* x      = (const float*)d_in[0];
    const float* h_prev = (const float*)d_in[1];
    const float* c_prev = (const float*)d_in[2];
    const float* Wx     = (const float*)d_in[3];
    const float* Wh     = (const float*)d_in[4];
    const float* bias   = (const float*)d_in[5];
    float* out = (float*)d_out;

    size_t packtot = A4TOT + W4TOT;
    pack_f16<<<(int)((packtot + 255) / 256), 256>>>(x, h_prev, Wx, Wh);

    cudaFuncSetAttribute(lstm_fused,
                         cudaFuncAttributeMaxDynamicSharedMemorySize, SMEM_TOTAL);
    dim3 grid(NB / BN, MB / BM);   // (32, 64)
    lstm_fused<<<grid, 256, SMEM_TOTAL>>>(bias, c_prev, out);
}